// round 11
// baseline (speedup 1.0000x reference)
#include <cuda_runtime.h>
#include <cuda_fp16.h>
#include <mma.h>
#include <math.h>
#include <stdint.h>

using namespace nvcuda;

// Problem constants
#define NN 50000
#define NE 800000
#define NF 128
#define NH 128
#define NH2 64
#define NG 512

#define NROWS_PAD 50048                       // 391 * 128, zero-padded rows
#define GEMM_BLOCKS ((NN + 127) / 128)        // 391
#define EDGE_BLOCKS ((NE + 255) / 256)        // 3125
#define CONV_BLOCKS ((NROWS_PAD * NF) / (256 * 8))  // 3128

// ---------------- scratch (static device globals; no allocation) -------------
__device__ __half d_xh[(size_t)NROWS_PAD * NF];  // x in fp16 (padded rows = 0)
__device__ __half d_h16[(size_t)NROWS_PAD * NF]; // activations fp16 (padded = 0)
__device__ __half d_g[(size_t)NN * NF];          // dinv-scaled projected features
__device__ float  d_dinv[NN];
__device__ int    d_cnt[NN];
__device__ int    d_rowptr[NN + 1];
__device__ int    d_cursor[NN];
__device__ int    d_col[NE];
__device__ float  d_pool[NG * NH2];
__device__ int    d_gcnt[NG];

// ---------------- init ------------------------------------------------------
__global__ void init_kernel() {
    int i = blockIdx.x * blockDim.x + threadIdx.x;
    if (i < NN) d_cnt[i] = 0;
    if (i < NG * NH2) d_pool[i] = 0.0f;
    if (i < NG) d_gcnt[i] = 0;
}

// ---------------- fused: degree count + x -> fp16 convert --------------------
// count branch: 1 edge/thread atomics (latency-bound, rides free).
// convert branch: 8 floats/thread -> uint4 of half2; pad rows set to 0.
__global__ void count_convert_kernel(const int* __restrict__ ei,
                                     const float* __restrict__ x) {
    if (blockIdx.x < EDGE_BLOCKS) {
        int e = blockIdx.x * blockDim.x + threadIdx.x;
        if (e < NE) atomicAdd(&d_cnt[ei[NE + e]], 1);
    } else {
        int t = (blockIdx.x - EDGE_BLOCKS) * blockDim.x + threadIdx.x;
        size_t e0 = (size_t)t * 8;   // NN*NF divisible by 8; grid covers pad exactly
        if (e0 < (size_t)NN * NF) {
            float4 f0 = *(const float4*)&x[e0];
            float4 f1 = *(const float4*)&x[e0 + 4];
            __half2 h[4];
            h[0] = __floats2half2_rn(f0.x, f0.y);
            h[1] = __floats2half2_rn(f0.z, f0.w);
            h[2] = __floats2half2_rn(f1.x, f1.y);
            h[3] = __floats2half2_rn(f1.z, f1.w);
            *(uint4*)&d_xh[e0] = *(uint4*)h;
        } else {
            uint4 z = make_uint4(0, 0, 0, 0);
            *(uint4*)&d_xh[e0] = z;
        }
    }
}

// ---------------- single-block scan: rowptr/cursor/dinv ----------------------
__global__ void scan_kernel() {
    __shared__ int warp_sums[32];
    __shared__ int s_carry;
    int tid = threadIdx.x, lane = tid & 31, wid = tid >> 5;
    if (tid == 0) s_carry = 0;
    __syncthreads();
    for (int base = 0; base < NN; base += 1024) {
        int i = base + tid;
        int v = (i < NN) ? d_cnt[i] : 0;
        int x = v;
        #pragma unroll
        for (int o = 1; o < 32; o <<= 1) {
            int t = __shfl_up_sync(0xFFFFFFFFu, x, o);
            if (lane >= o) x += t;
        }
        if (lane == 31) warp_sums[wid] = x;
        __syncthreads();
        if (wid == 0) {
            int w = warp_sums[lane];
            #pragma unroll
            for (int o = 1; o < 32; o <<= 1) {
                int t = __shfl_up_sync(0xFFFFFFFFu, w, o);
                if (lane >= o) w += t;
            }
            warp_sums[lane] = w;
        }
        __syncthreads();
        int warp_prefix = (wid > 0) ? warp_sums[wid - 1] : 0;
        int incl = s_carry + warp_prefix + x;
        int excl = incl - v;
        if (i < NN) {
            d_rowptr[i] = excl;
            d_cursor[i] = excl;
            d_dinv[i]   = rsqrtf((float)(v + 1));  // deg includes self-loop, >= 1
        }
        __syncthreads();
        if (tid == 1023) s_carry = incl;
        __syncthreads();
    }
    if (threadIdx.x == 0) d_rowptr[NN] = s_carry;
}

// ---------------- CSR fill (standalone: regs=16, occ ~77%) -------------------
__global__ void fill_kernel(const int* __restrict__ ei) {
    int e = blockIdx.x * blockDim.x + threadIdx.x;
    if (e < NE) {
        int s = ei[e];
        int d = ei[NE + e];
        int p = atomicAdd(&d_cursor[d], 1);
        d_col[p] = s;
    }
}

// ---------------- wmma fp16 GEMM: d_g = half(dinv[row] * (A @ W)) ------------
// 256 threads = 8 warps; block tile 128 x N; warp = 16-row strip.
// A fp16 in global (padded rows -> safe OOB-free loads); W staged fp16 in smem.
template <int K, int N, int SRC>   // SRC 0: A = d_xh, 1: A = d_h16
__global__ void gemm_wmma_kernel(const float* __restrict__ W) {
    constexpr int NFRAG = N / 16;
    constexpr int KSTEPS = K / 16;
    // union: W tile (mainloop) / epilogue bounce buffers
    __shared__ __align__(16) char raw[(K * N * 2) > (8 * 16 * 24 * 4)
                                      ? (K * N * 2) : (8 * 16 * 24 * 4)];
    __half* Wsh = (__half*)raw;
    const __half* __restrict__ A = (SRC == 0) ? d_xh : d_h16;

    int tid = threadIdx.x, warp = tid >> 5, lane = tid & 31;
    int mrow = blockIdx.x * 128 + warp * 16;

    // stage W (fp32 -> fp16), float2 -> half2
    for (int i = tid; i < K * N / 2; i += 256) {
        float2 w2 = *(const float2*)&W[i * 2];
        *(__half2*)&Wsh[i * 2] = __floats2half2_rn(w2.x, w2.y);
    }
    __syncthreads();

    wmma::fragment<wmma::accumulator, 16, 16, 16, float> acc[NFRAG];
    #pragma unroll
    for (int nf = 0; nf < NFRAG; nf++) wmma::fill_fragment(acc[nf], 0.0f);

    #pragma unroll
    for (int ks = 0; ks < KSTEPS; ks++) {
        wmma::fragment<wmma::matrix_a, 16, 16, 16, __half, wmma::row_major> a;
        wmma::load_matrix_sync(a, A + (size_t)mrow * K + ks * 16, K);
        #pragma unroll
        for (int nf = 0; nf < NFRAG; nf++) {
            wmma::fragment<wmma::matrix_b, 16, 16, 16, __half, wmma::row_major> b;
            wmma::load_matrix_sync(b, Wsh + ks * 16 * N + nf * 16, N);
            wmma::mma_sync(acc[nf], a, b, acc[nf]);
        }
    }

    // epilogue: bounce frags through smem (reusing W region), scale, fp16 store
    __syncthreads();
    float* Cs = (float*)raw + warp * (16 * 24);
    int r = lane >> 1;
    int c0 = (lane & 1) * 8;
    int row = mrow + r;
    float s = (row < NN) ? d_dinv[row] : 0.0f;
    #pragma unroll
    for (int nf = 0; nf < NFRAG; nf++) {
        wmma::store_matrix_sync(Cs, acc[nf], 24, wmma::mem_row_major);
        __syncwarp();
        if (row < NN) {
            float v[8];
            #pragma unroll
            for (int j = 0; j < 8; j++) v[j] = Cs[r * 24 + c0 + j] * s;
            __half2 h[4];
            #pragma unroll
            for (int j = 0; j < 4; j++)
                h[j] = __floats2half2_rn(v[2 * j], v[2 * j + 1]);
            *(uint4*)&d_g[(size_t)row * N + nf * 16 + c0] = *(uint4*)h;
        }
        __syncwarp();
    }
}

// ---------------- aggregation: out[i] = act(dinv[i]*(self + sum g[src]) + b) -
// block per node, F/2 threads; each thread owns 2 features via __half2.
// cols staged through smem (coalesced), gather loop unrolled 8 (MLP=8).
// MODE 0: relu -> d_h16 (fp16) ;  MODE 2: no relu, fused pooling atomics
template <int F, int MODE>
__global__ void agg_kernel(const float* __restrict__ bias,
                           const int* __restrict__ batch) {
    constexpr int T = F / 2;   // threads per block
    __shared__ int scol[T];
    int i = blockIdx.x;
    int f = threadIdx.x;       // 0..T-1, owns features 2f, 2f+1
    const __half2* __restrict__ g2 = (const __half2*)d_g;

    __half2 h = g2[(size_t)i * T + f];          // self-loop term
    float2 acc;
    acc.x = __low2float(h);
    acc.y = __high2float(h);

    int s = d_rowptr[i], e = d_rowptr[i + 1];
    for (int base = s; base < e; base += T) {
        int n = min(T, e - base);
        __syncthreads();
        if (f < n) scol[f] = d_col[base + f];
        __syncthreads();
        int k = 0;
        for (; k + 8 <= n; k += 8) {
            #pragma unroll
            for (int j = 0; j < 8; j++) {
                int c = scol[k + j];
                __half2 v = g2[(size_t)c * T + f];
                acc.x += __low2float(v);
                acc.y += __high2float(v);
            }
        }
        for (; k < n; k++) {
            int c = scol[k];
            __half2 v = g2[(size_t)c * T + f];
            acc.x += __low2float(v);
            acc.y += __high2float(v);
        }
    }

    float di = d_dinv[i];
    float2 b2 = ((const float2*)bias)[f];
    float rx = fmaf(di, acc.x, b2.x);
    float ry = fmaf(di, acc.y, b2.y);
    if (MODE == 0) {
        ((__half2*)d_h16)[(size_t)i * T + f] =
            __floats2half2_rn(fmaxf(rx, 0.0f), fmaxf(ry, 0.0f));
    } else {
        int b = batch[i];
        atomicAdd(&d_pool[b * NH2 + 2 * f + 0], rx);
        atomicAdd(&d_pool[b * NH2 + 2 * f + 1], ry);
        if (f == 0) atomicAdd(&d_gcnt[b], 1);
    }
}

// ---------------- final: sigmoid(mean) @ Wfc + bfc ---------------------------
__global__ void final_kernel(const float* __restrict__ Wfc,
                             const float* __restrict__ bfc,
                             float* __restrict__ out) {
    int gidx = blockIdx.x * (blockDim.x >> 5) + (threadIdx.x >> 5);
    int lane = threadIdx.x & 31;
    if (gidx >= NG) return;
    float cnt = fmaxf((float)d_gcnt[gidx], 1.0f);
    float s0 = d_pool[gidx * NH2 + lane];
    float s1 = d_pool[gidx * NH2 + 32 + lane];
    float z0 = 1.0f / (1.0f + expf(-s0 / cnt));
    float z1 = 1.0f / (1.0f + expf(-s1 / cnt));
    float p = z0 * Wfc[lane] + z1 * Wfc[lane + 32];
    #pragma unroll
    for (int o = 16; o > 0; o >>= 1) p += __shfl_down_sync(0xFFFFFFFFu, p, o);
    if (lane == 0) out[gidx] = p + bfc[0];
}

// ---------------- launch -----------------------------------------------------
extern "C" void kernel_launch(void* const* d_in, const int* in_sizes, int n_in,
                              void* d_out, int out_size) {
    const float* x     = (const float*)d_in[0];
    const int*   ei    = (const int*)d_in[1];
    const int*   batch = (const int*)d_in[2];
    const float* W1    = (const float*)d_in[3];
    const float* b1    = (const float*)d_in[4];
    const float* W2    = (const float*)d_in[5];
    const float* b2    = (const float*)d_in[6];
    const float* W3    = (const float*)d_in[7];
    const float* b3    = (const float*)d_in[8];
    const float* Wfc   = (const float*)d_in[9];
    const float* bfc   = (const float*)d_in[10];
    float* out = (float*)d_out;

    init_kernel<<<(NN + 255) / 256, 256>>>();
    count_convert_kernel<<<EDGE_BLOCKS + CONV_BLOCKS, 256>>>(ei, x);
    scan_kernel<<<1, 1024>>>();
    fill_kernel<<<EDGE_BLOCKS, 256>>>(ei);

    // layer 1: 128 -> 128, relu
    gemm_wmma_kernel<128, 128, 0><<<GEMM_BLOCKS, 256>>>(W1);
    agg_kernel<128, 0><<<NN, 64>>>(b1, batch);

    // layer 2: 128 -> 64, relu
    gemm_wmma_kernel<128, 64, 1><<<GEMM_BLOCKS, 256>>>(W2);
    agg_kernel<64, 0><<<NN, 32>>>(b2, batch);

    // layer 3: 64 -> 64, no relu, fused pooling
    gemm_wmma_kernel<64, 64, 1><<<GEMM_BLOCKS, 256>>>(W3);
    agg_kernel<64, 2><<<NN, 32>>>(b3, batch);

    final_kernel<<<(NG + 7) / 8, 256>>>(Wfc, bfc, out);
}

// round 13
// speedup vs baseline: 1.0074x; 1.0074x over previous
#include <cuda_runtime.h>
#include <cuda_fp16.h>
#include <mma.h>
#include <math.h>
#include <stdint.h>

using namespace nvcuda;

// Problem constants
#define NN 50000
#define NE 800000
#define NF 128
#define NH 128
#define NH2 64
#define NG 512

#define NROWS_PAD 50048                       // 391 * 128 = 782 * 64, zero-padded
#define EDGE_BLOCKS ((NE + 255) / 256)        // 3125
#define CONV_BLOCKS ((NROWS_PAD * NF) / (256 * 8))  // 3128

// smem bytes for gemm_wmma_kernel<K,N,*>: W tile + padded A tile (>= 12KB epi)
#define GEMM_SMEM(K, N) ((K) * (N) * 2 + (((N) == 128) ? 64 : 128) * ((K) + 8) * 2)

// ---------------- scratch (static device globals; no allocation) -------------
__device__ __half d_xh[(size_t)NROWS_PAD * NF];  // x in fp16 (padded rows = 0)
__device__ __half d_h16[(size_t)NROWS_PAD * NF]; // activations fp16
__device__ __half d_g[(size_t)NN * NF];          // dinv-scaled projected features
__device__ float  d_dinv[NN];
__device__ int    d_cnt[NN];
__device__ int    d_rowptr[NN + 1];
__device__ int    d_cursor[NN];
__device__ int    d_col[NE];
__device__ float  d_pool[NG * NH2];
__device__ int    d_gcnt[NG];

// ---------------- init ------------------------------------------------------
__global__ void init_kernel() {
    int i = blockIdx.x * blockDim.x + threadIdx.x;
    if (i < NN) d_cnt[i] = 0;
    if (i < NG * NH2) d_pool[i] = 0.0f;
    if (i < NG) d_gcnt[i] = 0;
}

// ---------------- fused: degree count + x -> fp16 convert --------------------
__global__ void count_convert_kernel(const int* __restrict__ ei,
                                     const float* __restrict__ x) {
    if (blockIdx.x < EDGE_BLOCKS) {
        int e = blockIdx.x * blockDim.x + threadIdx.x;
        if (e < NE) atomicAdd(&d_cnt[ei[NE + e]], 1);
    } else {
        int t = (blockIdx.x - EDGE_BLOCKS) * blockDim.x + threadIdx.x;
        size_t e0 = (size_t)t * 8;   // grid covers pad exactly
        if (e0 < (size_t)NN * NF) {
            float4 f0 = *(const float4*)&x[e0];
            float4 f1 = *(const float4*)&x[e0 + 4];
            __half2 h[4];
            h[0] = __floats2half2_rn(f0.x, f0.y);
            h[1] = __floats2half2_rn(f0.z, f0.w);
            h[2] = __floats2half2_rn(f1.x, f1.y);
            h[3] = __floats2half2_rn(f1.z, f1.w);
            *(uint4*)&d_xh[e0] = *(uint4*)h;
        } else {
            uint4 z = make_uint4(0, 0, 0, 0);
            *(uint4*)&d_xh[e0] = z;
        }
    }
}

// ---------------- single-block scan: rowptr/cursor/dinv ----------------------
__global__ void scan_kernel() {
    __shared__ int warp_sums[32];
    __shared__ int s_carry;
    int tid = threadIdx.x, lane = tid & 31, wid = tid >> 5;
    if (tid == 0) s_carry = 0;
    __syncthreads();
    for (int base = 0; base < NN; base += 1024) {
        int i = base + tid;
        int v = (i < NN) ? d_cnt[i] : 0;
        int x = v;
        #pragma unroll
        for (int o = 1; o < 32; o <<= 1) {
            int t = __shfl_up_sync(0xFFFFFFFFu, x, o);
            if (lane >= o) x += t;
        }
        if (lane == 31) warp_sums[wid] = x;
        __syncthreads();
        if (wid == 0) {
            int w = warp_sums[lane];
            #pragma unroll
            for (int o = 1; o < 32; o <<= 1) {
                int t = __shfl_up_sync(0xFFFFFFFFu, w, o);
                if (lane >= o) w += t;
            }
            warp_sums[lane] = w;
        }
        __syncthreads();
        int warp_prefix = (wid > 0) ? warp_sums[wid - 1] : 0;
        int incl = s_carry + warp_prefix + x;
        int excl = incl - v;
        if (i < NN) {
            d_rowptr[i] = excl;
            d_cursor[i] = excl;
            d_dinv[i]   = rsqrtf((float)(v + 1));  // deg includes self-loop, >= 1
        }
        __syncthreads();
        if (tid == 1023) s_carry = incl;
        __syncthreads();
    }
    if (threadIdx.x == 0) d_rowptr[NN] = s_carry;
}

// ---------------- CSR fill (standalone: regs=16, occ ~77%) -------------------
__global__ void fill_kernel(const int* __restrict__ ei) {
    int e = blockIdx.x * blockDim.x + threadIdx.x;
    if (e < NE) {
        int s = ei[e];
        int d = ei[NE + e];
        int p = atomicAdd(&d_cursor[d], 1);
        d_col[p] = s;
    }
}

// ---------------- wmma fp16 GEMM: d_g = half(dinv[row] * (A @ W)) ------------
// 256 threads = 8 warps, warp tile 16x64 (4 frags). A staged in smem (coalesced,
// +8-half row pad vs LDSM conflicts); W staged fp16 in smem; sync-free mainloop.
// Dynamic smem (> 48KB static cap); size = GEMM_SMEM(K, N).
template <int K, int N, int SRC>   // SRC 0: A = d_xh, 1: A = d_h16
__global__ void gemm_wmma_kernel(const float* __restrict__ W) {
    constexpr int N_WARPS = N / 64;          // 2 (N=128) or 1 (N=64)
    constexpr int M_WARPS = 8 / N_WARPS;     // 4 or 8
    constexpr int M_TILE  = M_WARPS * 16;    // 64 or 128
    constexpr int PK = K + 8;                // padded A row (halves)
    constexpr int KSTEPS = K / 16;
    extern __shared__ __align__(16) char raw[];
    __half* Wsh = (__half*)raw;
    __half* As  = (__half*)(raw + K * N * 2);
    const __half* __restrict__ A = (SRC == 0) ? d_xh : d_h16;

    int tid = threadIdx.x, warp = tid >> 5, lane = tid & 31;
    int warp_m = warp % M_WARPS;
    int warp_n = warp / M_WARPS;
    int m0 = blockIdx.x * M_TILE;

    // stage W (fp32 -> fp16)
    for (int i = tid; i < K * N / 2; i += 256) {
        float2 w2 = *(const float2*)&W[i * 2];
        *(__half2*)&Wsh[i * 2] = __floats2half2_rn(w2.x, w2.y);
    }
    // stage A tile coalesced (uint4 = 8 halves), padded row stride
    for (int idx = tid; idx < M_TILE * K / 8; idx += 256) {
        int r = idx / (K / 8);
        int c = (idx % (K / 8)) * 8;
        *(uint4*)&As[r * PK + c] = *(const uint4*)&A[(size_t)(m0 + r) * K + c];
    }
    __syncthreads();

    wmma::fragment<wmma::accumulator, 16, 16, 16, float> acc[4];
    #pragma unroll
    for (int nf = 0; nf < 4; nf++) wmma::fill_fragment(acc[nf], 0.0f);

    #pragma unroll
    for (int ks = 0; ks < KSTEPS; ks++) {
        wmma::fragment<wmma::matrix_a, 16, 16, 16, __half, wmma::row_major> a;
        wmma::load_matrix_sync(a, As + warp_m * 16 * PK + ks * 16, PK);
        #pragma unroll
        for (int nf = 0; nf < 4; nf++) {
            wmma::fragment<wmma::matrix_b, 16, 16, 16, __half, wmma::row_major> b;
            wmma::load_matrix_sync(b, Wsh + ks * 16 * N + warp_n * 64 + nf * 16, N);
            wmma::mma_sync(acc[nf], a, b, acc[nf]);
        }
    }

    // epilogue: bounce frags through smem (reuse), scale by dinv, fp16 store
    __syncthreads();
    float* Cs = (float*)raw + warp * (16 * 24);
    int r = lane >> 1;
    int c0 = (lane & 1) * 8;
    int row = m0 + warp_m * 16 + r;
    float s = (row < NN) ? d_dinv[row] : 0.0f;
    #pragma unroll
    for (int nf = 0; nf < 4; nf++) {
        wmma::store_matrix_sync(Cs, acc[nf], 24, wmma::mem_row_major);
        __syncwarp();
        if (row < NN) {
            float v[8];
            #pragma unroll
            for (int j = 0; j < 8; j++) v[j] = Cs[r * 24 + c0 + j] * s;
            __half2 h[4];
            #pragma unroll
            for (int j = 0; j < 4; j++)
                h[j] = __floats2half2_rn(v[2 * j], v[2 * j + 1]);
            *(uint4*)&d_g[(size_t)row * N + warp_n * 64 + nf * 16 + c0] = *(uint4*)h;
        }
        __syncwarp();
    }
}

// ---------------- aggregation: out[i] = act(dinv[i]*(self + sum g[src]) + b) -
// block per node, F/2 threads; each thread owns 2 features via __half2.
// MODE 0: relu -> d_h16 (fp16) ;  MODE 2: no relu, fused pooling atomics
template <int F, int MODE>
__global__ void agg_kernel(const float* __restrict__ bias,
                           const int* __restrict__ batch) {
    constexpr int T = F / 2;   // threads per block
    __shared__ int scol[T];
    int i = blockIdx.x;
    int f = threadIdx.x;       // owns features 2f, 2f+1
    const __half2* __restrict__ g2 = (const __half2*)d_g;

    __half2 h = g2[(size_t)i * T + f];          // self-loop term
    float2 acc;
    acc.x = __low2float(h);
    acc.y = __high2float(h);

    int s = d_rowptr[i], e = d_rowptr[i + 1];
    for (int base = s; base < e; base += T) {
        int n = min(T, e - base);
        __syncthreads();
        if (f < n) scol[f] = d_col[base + f];
        __syncthreads();
        int k = 0;
        for (; k + 8 <= n; k += 8) {
            #pragma unroll
            for (int j = 0; j < 8; j++) {
                int c = scol[k + j];
                __half2 v = g2[(size_t)c * T + f];
                acc.x += __low2float(v);
                acc.y += __high2float(v);
            }
        }
        for (; k < n; k++) {
            int c = scol[k];
            __half2 v = g2[(size_t)c * T + f];
            acc.x += __low2float(v);
            acc.y += __high2float(v);
        }
    }

    float di = d_dinv[i];
    float2 b2 = ((const float2*)bias)[f];
    float rx = fmaf(di, acc.x, b2.x);
    float ry = fmaf(di, acc.y, b2.y);
    if (MODE == 0) {
        ((__half2*)d_h16)[(size_t)i * T + f] =
            __floats2half2_rn(fmaxf(rx, 0.0f), fmaxf(ry, 0.0f));
    } else {
        int b = batch[i];
        atomicAdd(&d_pool[b * NH2 + 2 * f + 0], rx);
        atomicAdd(&d_pool[b * NH2 + 2 * f + 1], ry);
        if (f == 0) atomicAdd(&d_gcnt[b], 1);
    }
}

// ---------------- final: sigmoid(mean) @ Wfc + bfc ---------------------------
__global__ void final_kernel(const float* __restrict__ Wfc,
                             const float* __restrict__ bfc,
                             float* __restrict__ out) {
    int gidx = blockIdx.x * (blockDim.x >> 5) + (threadIdx.x >> 5);
    int lane = threadIdx.x & 31;
    if (gidx >= NG) return;
    float cnt = fmaxf((float)d_gcnt[gidx], 1.0f);
    float s0 = d_pool[gidx * NH2 + lane];
    float s1 = d_pool[gidx * NH2 + 32 + lane];
    float z0 = 1.0f / (1.0f + expf(-s0 / cnt));
    float z1 = 1.0f / (1.0f + expf(-s1 / cnt));
    float p = z0 * Wfc[lane] + z1 * Wfc[lane + 32];
    #pragma unroll
    for (int o = 16; o > 0; o >>= 1) p += __shfl_down_sync(0xFFFFFFFFu, p, o);
    if (lane == 0) out[gidx] = p + bfc[0];
}

// ---------------- launch -----------------------------------------------------
extern "C" void kernel_launch(void* const* d_in, const int* in_sizes, int n_in,
                              void* d_out, int out_size) {
    const float* x     = (const float*)d_in[0];
    const int*   ei    = (const int*)d_in[1];
    const int*   batch = (const int*)d_in[2];
    const float* W1    = (const float*)d_in[3];
    const float* b1    = (const float*)d_in[4];
    const float* W2    = (const float*)d_in[5];
    const float* b2    = (const float*)d_in[6];
    const float* W3    = (const float*)d_in[7];
    const float* b3    = (const float*)d_in[8];
    const float* Wfc   = (const float*)d_in[9];
    const float* bfc   = (const float*)d_in[10];
    float* out = (float*)d_out;

    // raise dynamic-smem caps (host attribute set; idempotent, capture-safe)
    cudaFuncSetAttribute(gemm_wmma_kernel<128, 128, 0>,
                         cudaFuncAttributeMaxDynamicSharedMemorySize,
                         GEMM_SMEM(128, 128));
    cudaFuncSetAttribute(gemm_wmma_kernel<128, 64, 1>,
                         cudaFuncAttributeMaxDynamicSharedMemorySize,
                         GEMM_SMEM(128, 64));
    cudaFuncSetAttribute(gemm_wmma_kernel<64, 64, 1>,
                         cudaFuncAttributeMaxDynamicSharedMemorySize,
                         GEMM_SMEM(64, 64));

    init_kernel<<<(NN + 255) / 256, 256>>>();
    count_convert_kernel<<<EDGE_BLOCKS + CONV_BLOCKS, 256>>>(ei, x);
    scan_kernel<<<1, 1024>>>();
    fill_kernel<<<EDGE_BLOCKS, 256>>>(ei);

    // layer 1: 128 -> 128, relu  (M_TILE=64 -> 782 blocks)
    gemm_wmma_kernel<128, 128, 0>
        <<<NROWS_PAD / 64, 256, GEMM_SMEM(128, 128)>>>(W1);
    agg_kernel<128, 0><<<NN, 64>>>(b1, batch);

    // layer 2: 128 -> 64, relu   (M_TILE=128 -> 391 blocks)
    gemm_wmma_kernel<128, 64, 1>
        <<<NROWS_PAD / 128, 256, GEMM_SMEM(128, 64)>>>(W2);
    agg_kernel<64, 0><<<NN, 32>>>(b2, batch);

    // layer 3: 64 -> 64, no relu, fused pooling
    gemm_wmma_kernel<64, 64, 1>
        <<<NROWS_PAD / 128, 256, GEMM_SMEM(64, 64)>>>(W3);
    agg_kernel<64, 2><<<NN, 32>>>(b3, batch);

    final_kernel<<<(NG + 7) / 8, 256>>>(Wfc, bfc, out);
}

// round 14
// speedup vs baseline: 1.2145x; 1.2055x over previous
#include <cuda_runtime.h>
#include <cuda_fp16.h>
#include <mma.h>
#include <math.h>
#include <stdint.h>

using namespace nvcuda;

// Problem constants
#define NN 50000
#define NE 800000
#define NF 128
#define NH 128
#define NH2 64
#define NG 512

#define NROWS_PAD 50048                       // 391 * 128 = 782 * 64, zero-padded
#define EDGE_BLOCKS ((NE + 255) / 256)        // 3125
#define CONV_BLOCKS ((NROWS_PAD * NF) / (256 * 8))  // 3128
#define GEMM1_BLOCKS (NROWS_PAD / 64)         // 782

// smem bytes: padded W tile + padded A tile (both conflict-free LDSM strides)
#define GEMM_SMEM(K, N) \
    ((K) * ((N) + 8) * 2 + (((N) == 128) ? 64 : 128) * ((K) + 8) * 2)

// ---------------- scratch (static device globals; no allocation) -------------
__device__ __half d_xh[(size_t)NROWS_PAD * NF];  // x in fp16 (padded rows = 0)
__device__ __half d_h16[(size_t)NROWS_PAD * NF]; // activations fp16
__device__ __half d_g[(size_t)NN * NF];          // dinv-scaled projected features
__device__ float  d_dinv[NN];
__device__ int    d_cnt[NN];
__device__ int    d_rowptr[NN + 1];
__device__ int    d_cursor[NN];
__device__ int    d_col[NE];
__device__ float  d_pool[NG * NH2];
__device__ int    d_gcnt[NG];

// ---------------- init ------------------------------------------------------
__global__ void init_kernel() {
    int i = blockIdx.x * blockDim.x + threadIdx.x;
    if (i < NN) d_cnt[i] = 0;
    if (i < NG * NH2) d_pool[i] = 0.0f;
    if (i < NG) d_gcnt[i] = 0;
}

// ---------------- fused: degree count + x -> fp16 convert --------------------
__global__ void count_convert_kernel(const int* __restrict__ ei,
                                     const float* __restrict__ x) {
    if (blockIdx.x < EDGE_BLOCKS) {
        int e = blockIdx.x * blockDim.x + threadIdx.x;
        if (e < NE) atomicAdd(&d_cnt[ei[NE + e]], 1);
    } else {
        int t = (blockIdx.x - EDGE_BLOCKS) * blockDim.x + threadIdx.x;
        size_t e0 = (size_t)t * 8;   // grid covers pad exactly
        if (e0 < (size_t)NN * NF) {
            float4 f0 = *(const float4*)&x[e0];
            float4 f1 = *(const float4*)&x[e0 + 4];
            __half2 h[4];
            h[0] = __floats2half2_rn(f0.x, f0.y);
            h[1] = __floats2half2_rn(f0.z, f0.w);
            h[2] = __floats2half2_rn(f1.x, f1.y);
            h[3] = __floats2half2_rn(f1.z, f1.w);
            *(uint4*)&d_xh[e0] = *(uint4*)h;
        } else {
            uint4 z = make_uint4(0, 0, 0, 0);
            *(uint4*)&d_xh[e0] = z;
        }
    }
}

// ---------------- single-block scan: rowptr/cursor/dinv ----------------------
__global__ void scan_kernel() {
    __shared__ int warp_sums[32];
    __shared__ int s_carry;
    int tid = threadIdx.x, lane = tid & 31, wid = tid >> 5;
    if (tid == 0) s_carry = 0;
    __syncthreads();
    for (int base = 0; base < NN; base += 1024) {
        int i = base + tid;
        int v = (i < NN) ? d_cnt[i] : 0;
        int x = v;
        #pragma unroll
        for (int o = 1; o < 32; o <<= 1) {
            int t = __shfl_up_sync(0xFFFFFFFFu, x, o);
            if (lane >= o) x += t;
        }
        if (lane == 31) warp_sums[wid] = x;
        __syncthreads();
        if (wid == 0) {
            int w = warp_sums[lane];
            #pragma unroll
            for (int o = 1; o < 32; o <<= 1) {
                int t = __shfl_up_sync(0xFFFFFFFFu, w, o);
                if (lane >= o) w += t;
            }
            warp_sums[lane] = w;
        }
        __syncthreads();
        int warp_prefix = (wid > 0) ? warp_sums[wid - 1] : 0;
        int incl = s_carry + warp_prefix + x;
        int excl = incl - v;
        if (i < NN) {
            d_rowptr[i] = excl;
            d_cursor[i] = excl;
            d_dinv[i]   = rsqrtf((float)(v + 1));  // deg includes self-loop, >= 1
        }
        __syncthreads();
        if (tid == 1023) s_carry = incl;
        __syncthreads();
    }
    if (threadIdx.x == 0) d_rowptr[NN] = s_carry;
}

// ---------------- wmma fp16 GEMM body: d_g = half(dinv[row] * (A @ W)) -------
// 256 threads = 8 warps, warp tile 16x64. A smem-staged (+8-half row pad);
// W smem-staged with +8-half row pad (conflict-free B LDSM). Sync-free mainloop.
template <int K, int N, int SRC>   // SRC 0: A = d_xh, 1: A = d_h16
__device__ __forceinline__ void gemm_wmma_body(int bid, const float* __restrict__ W,
                                               char* raw) {
    constexpr int N_WARPS = N / 64;          // 2 (N=128) or 1 (N=64)
    constexpr int M_WARPS = 8 / N_WARPS;     // 4 or 8
    constexpr int M_TILE  = M_WARPS * 16;    // 64 or 128
    constexpr int PK = K + 8;                // padded A row (halves)
    constexpr int PW = N + 8;                // padded W row (halves)
    constexpr int KSTEPS = K / 16;
    __half* Wsh = (__half*)raw;
    __half* As  = (__half*)(raw + K * PW * 2);
    const __half* __restrict__ A = (SRC == 0) ? d_xh : d_h16;

    int tid = threadIdx.x, warp = tid >> 5, lane = tid & 31;
    int warp_m = warp % M_WARPS;
    int warp_n = warp / M_WARPS;
    int m0 = bid * M_TILE;

    // stage W (fp32 -> fp16), padded row stride
    for (int i = tid; i < K * N / 2; i += 256) {
        int r = (i * 2) / N, c = (i * 2) % N;
        float2 w2 = *(const float2*)&W[r * N + c];
        *(__half2*)&Wsh[r * PW + c] = __floats2half2_rn(w2.x, w2.y);
    }
    // stage A tile coalesced (uint4 = 8 halves), padded row stride
    for (int idx = tid; idx < M_TILE * K / 8; idx += 256) {
        int r = idx / (K / 8);
        int c = (idx % (K / 8)) * 8;
        *(uint4*)&As[r * PK + c] = *(const uint4*)&A[(size_t)(m0 + r) * K + c];
    }
    __syncthreads();

    wmma::fragment<wmma::accumulator, 16, 16, 16, float> acc[4];
    #pragma unroll
    for (int nf = 0; nf < 4; nf++) wmma::fill_fragment(acc[nf], 0.0f);

    #pragma unroll
    for (int ks = 0; ks < KSTEPS; ks++) {
        wmma::fragment<wmma::matrix_a, 16, 16, 16, __half, wmma::row_major> a;
        wmma::load_matrix_sync(a, As + warp_m * 16 * PK + ks * 16, PK);
        #pragma unroll
        for (int nf = 0; nf < 4; nf++) {
            wmma::fragment<wmma::matrix_b, 16, 16, 16, __half, wmma::row_major> b;
            wmma::load_matrix_sync(b, Wsh + ks * 16 * PW + warp_n * 64 + nf * 16, PW);
            wmma::mma_sync(acc[nf], a, b, acc[nf]);
        }
    }

    // epilogue: bounce frags through smem (reuse), scale by dinv, fp16 store
    __syncthreads();
    float* Cs = (float*)raw + warp * (16 * 24);
    int r = lane >> 1;
    int c0 = (lane & 1) * 8;
    int row = m0 + warp_m * 16 + r;
    float s = (row < NN) ? d_dinv[row] : 0.0f;
    #pragma unroll
    for (int nf = 0; nf < 4; nf++) {
        wmma::store_matrix_sync(Cs, acc[nf], 24, wmma::mem_row_major);
        __syncwarp();
        if (row < NN) {
            float v[8];
            #pragma unroll
            for (int j = 0; j < 8; j++) v[j] = Cs[r * 24 + c0 + j] * s;
            __half2 h[4];
            #pragma unroll
            for (int j = 0; j < 4; j++)
                h[j] = __floats2half2_rn(v[2 * j], v[2 * j + 1]);
            *(uint4*)&d_g[(size_t)row * N + warp_n * 64 + nf * 16 + c0] = *(uint4*)h;
        }
        __syncwarp();
    }
}

template <int K, int N, int SRC>
__global__ void gemm_wmma_kernel(const float* __restrict__ W) {
    extern __shared__ __align__(16) char raw[];
    gemm_wmma_body<K, N, SRC>(blockIdx.x, W, raw);
}

// ---------------- fused: gemm1 (blocks 0..781) + CSR fill (rest) -------------
__global__ void gemm1_fill_kernel(const float* __restrict__ W1,
                                  const int* __restrict__ ei) {
    extern __shared__ __align__(16) char raw[];
    if (blockIdx.x < GEMM1_BLOCKS) {
        gemm_wmma_body<128, 128, 0>(blockIdx.x, W1, raw);
    } else {
        int e = (blockIdx.x - GEMM1_BLOCKS) * blockDim.x + threadIdx.x;
        if (e < NE) {
            int s = ei[e];
            int d = ei[NE + e];
            int p = atomicAdd(&d_cursor[d], 1);
            d_col[p] = s;
        }
    }
}

// ---------------- aggregation: out[i] = act(dinv[i]*(self + sum g[src]) + b) -
// block per node, F/2 threads; each thread owns 2 features via __half2.
// MODE 0: relu -> d_h16 (fp16) ;  MODE 2: no relu, fused pooling atomics
template <int F, int MODE>
__global__ void agg_kernel(const float* __restrict__ bias,
                           const int* __restrict__ batch) {
    constexpr int T = F / 2;   // threads per block
    __shared__ int scol[T];
    int i = blockIdx.x;
    int f = threadIdx.x;       // owns features 2f, 2f+1
    const __half2* __restrict__ g2 = (const __half2*)d_g;

    __half2 h = g2[(size_t)i * T + f];          // self-loop term
    float2 acc;
    acc.x = __low2float(h);
    acc.y = __high2float(h);

    int s = d_rowptr[i], e = d_rowptr[i + 1];
    for (int base = s; base < e; base += T) {
        int n = min(T, e - base);
        __syncthreads();
        if (f < n) scol[f] = d_col[base + f];
        __syncthreads();
        int k = 0;
        for (; k + 8 <= n; k += 8) {
            #pragma unroll
            for (int j = 0; j < 8; j++) {
                int c = scol[k + j];
                __half2 v = g2[(size_t)c * T + f];
                acc.x += __low2float(v);
                acc.y += __high2float(v);
            }
        }
        for (; k < n; k++) {
            int c = scol[k];
            __half2 v = g2[(size_t)c * T + f];
            acc.x += __low2float(v);
            acc.y += __high2float(v);
        }
    }

    float di = d_dinv[i];
    float2 b2 = ((const float2*)bias)[f];
    float rx = fmaf(di, acc.x, b2.x);
    float ry = fmaf(di, acc.y, b2.y);
    if (MODE == 0) {
        ((__half2*)d_h16)[(size_t)i * T + f] =
            __floats2half2_rn(fmaxf(rx, 0.0f), fmaxf(ry, 0.0f));
    } else {
        int b = batch[i];
        atomicAdd(&d_pool[b * NH2 + 2 * f + 0], rx);
        atomicAdd(&d_pool[b * NH2 + 2 * f + 1], ry);
        if (f == 0) atomicAdd(&d_gcnt[b], 1);
    }
}

// ---------------- final: sigmoid(mean) @ Wfc + bfc ---------------------------
__global__ void final_kernel(const float* __restrict__ Wfc,
                             const float* __restrict__ bfc,
                             float* __restrict__ out) {
    int gidx = blockIdx.x * (blockDim.x >> 5) + (threadIdx.x >> 5);
    int lane = threadIdx.x & 31;
    if (gidx >= NG) return;
    float cnt = fmaxf((float)d_gcnt[gidx], 1.0f);
    float s0 = d_pool[gidx * NH2 + lane];
    float s1 = d_pool[gidx * NH2 + 32 + lane];
    float z0 = 1.0f / (1.0f + expf(-s0 / cnt));
    float z1 = 1.0f / (1.0f + expf(-s1 / cnt));
    float p = z0 * Wfc[lane] + z1 * Wfc[lane + 32];
    #pragma unroll
    for (int o = 16; o > 0; o >>= 1) p += __shfl_down_sync(0xFFFFFFFFu, p, o);
    if (lane == 0) out[gidx] = p + bfc[0];
}

// ---------------- launch -----------------------------------------------------
extern "C" void kernel_launch(void* const* d_in, const int* in_sizes, int n_in,
                              void* d_out, int out_size) {
    const float* x     = (const float*)d_in[0];
    const int*   ei    = (const int*)d_in[1];
    const int*   batch = (const int*)d_in[2];
    const float* W1    = (const float*)d_in[3];
    const float* b1    = (const float*)d_in[4];
    const float* W2    = (const float*)d_in[5];
    const float* b2    = (const float*)d_in[6];
    const float* W3    = (const float*)d_in[7];
    const float* b3    = (const float*)d_in[8];
    const float* Wfc   = (const float*)d_in[9];
    const float* bfc   = (const float*)d_in[10];
    float* out = (float*)d_out;

    // raise dynamic-smem caps (host attribute set; idempotent, capture-safe)
    cudaFuncSetAttribute(gemm1_fill_kernel,
                         cudaFuncAttributeMaxDynamicSharedMemorySize,
                         GEMM_SMEM(128, 128));
    cudaFuncSetAttribute(gemm_wmma_kernel<128, 64, 1>,
                         cudaFuncAttributeMaxDynamicSharedMemorySize,
                         GEMM_SMEM(128, 64));
    cudaFuncSetAttribute(gemm_wmma_kernel<64, 64, 1>,
                         cudaFuncAttributeMaxDynamicSharedMemorySize,
                         GEMM_SMEM(64, 64));

    init_kernel<<<(NN + 255) / 256, 256>>>();
    count_convert_kernel<<<EDGE_BLOCKS + CONV_BLOCKS, 256>>>(ei, x);
    scan_kernel<<<1, 1024>>>();

    // layer 1 GEMM fused with CSR fill (position 4 -> gets profiled)
    gemm1_fill_kernel
        <<<GEMM1_BLOCKS + EDGE_BLOCKS, 256, GEMM_SMEM(128, 128)>>>(W1, ei);
    agg_kernel<128, 0><<<NN, 64>>>(b1, batch);

    // layer 2: 128 -> 64, relu
    gemm_wmma_kernel<128, 64, 1>
        <<<NROWS_PAD / 128, 256, GEMM_SMEM(128, 64)>>>(W2);
    agg_kernel<64, 0><<<NN, 32>>>(b2, batch);

    // layer 3: 64 -> 64, no relu, fused pooling
    gemm_wmma_kernel<64, 64, 1>
        <<<NROWS_PAD / 128, 256, GEMM_SMEM(64, 64)>>>(W3);
    agg_kernel<64, 2><<<NN, 32>>>(b3, batch);

    final_kernel<<<(NG + 7) / 8, 256>>>(Wfc, bfc, out);
}

// round 15
// speedup vs baseline: 1.3050x; 1.0745x over previous
#include <cuda_runtime.h>
#include <cuda_fp16.h>
#include <mma.h>
#include <math.h>
#include <stdint.h>

using namespace nvcuda;

// Problem constants
#define NN 50000
#define NE 800000
#define NF 128
#define NH 128
#define NH2 64
#define NG 512

#define NROWS_PAD 50048                       // 391 * 128 = 782 * 64, zero-padded
#define EDGE_BLOCKS ((NE + 255) / 256)        // 3125
#define CONV_BLOCKS ((NROWS_PAD * NF) / (256 * 8))  // 3128
#define GEMM1_BLOCKS (NROWS_PAD / 64)         // 782

// smem bytes: padded W tile + padded A tile (both conflict-free LDSM strides)
#define GEMM_SMEM(K, N) \
    ((K) * ((N) + 8) * 2 + (((N) == 128) ? 64 : 128) * ((K) + 8) * 2)

// ---------------- scratch (static device globals; no allocation) -------------
__device__ __half d_xh[(size_t)NROWS_PAD * NF];  // x in fp16 (padded rows = 0)
__device__ __half d_h16[(size_t)NROWS_PAD * NF]; // activations fp16
__device__ __half d_g[(size_t)NN * NF];          // dinv-scaled projected features
__device__ float  d_dinv[NN];
__device__ int    d_cnt[NN];
__device__ int    d_rowptr[NN + 1];
__device__ int    d_cursor[NN];
__device__ int    d_col[NE];
__device__ float  d_pool[NG * NH2];
__device__ int    d_gcnt[NG];

// ---------------- init ------------------------------------------------------
__global__ void init_kernel() {
    int i = blockIdx.x * blockDim.x + threadIdx.x;
    if (i < NN) d_cnt[i] = 0;
    if (i < NG * NH2) d_pool[i] = 0.0f;
    if (i < NG) d_gcnt[i] = 0;
}

// ---------------- fused: degree count + x -> fp16 convert --------------------
__global__ void count_convert_kernel(const int* __restrict__ ei,
                                     const float* __restrict__ x) {
    if (blockIdx.x < EDGE_BLOCKS) {
        int e = blockIdx.x * blockDim.x + threadIdx.x;
        if (e < NE) atomicAdd(&d_cnt[ei[NE + e]], 1);
    } else {
        int t = (blockIdx.x - EDGE_BLOCKS) * blockDim.x + threadIdx.x;
        size_t e0 = (size_t)t * 8;   // grid covers pad exactly
        if (e0 < (size_t)NN * NF) {
            float4 f0 = *(const float4*)&x[e0];
            float4 f1 = *(const float4*)&x[e0 + 4];
            __half2 h[4];
            h[0] = __floats2half2_rn(f0.x, f0.y);
            h[1] = __floats2half2_rn(f0.z, f0.w);
            h[2] = __floats2half2_rn(f1.x, f1.y);
            h[3] = __floats2half2_rn(f1.z, f1.w);
            *(uint4*)&d_xh[e0] = *(uint4*)h;
        } else {
            uint4 z = make_uint4(0, 0, 0, 0);
            *(uint4*)&d_xh[e0] = z;
        }
    }
}

// ---------------- single-block scan: rowptr/cursor/dinv ----------------------
__global__ void scan_kernel() {
    __shared__ int warp_sums[32];
    __shared__ int s_carry;
    int tid = threadIdx.x, lane = tid & 31, wid = tid >> 5;
    if (tid == 0) s_carry = 0;
    __syncthreads();
    for (int base = 0; base < NN; base += 1024) {
        int i = base + tid;
        int v = (i < NN) ? d_cnt[i] : 0;
        int x = v;
        #pragma unroll
        for (int o = 1; o < 32; o <<= 1) {
            int t = __shfl_up_sync(0xFFFFFFFFu, x, o);
            if (lane >= o) x += t;
        }
        if (lane == 31) warp_sums[wid] = x;
        __syncthreads();
        if (wid == 0) {
            int w = warp_sums[lane];
            #pragma unroll
            for (int o = 1; o < 32; o <<= 1) {
                int t = __shfl_up_sync(0xFFFFFFFFu, w, o);
                if (lane >= o) w += t;
            }
            warp_sums[lane] = w;
        }
        __syncthreads();
        int warp_prefix = (wid > 0) ? warp_sums[wid - 1] : 0;
        int incl = s_carry + warp_prefix + x;
        int excl = incl - v;
        if (i < NN) {
            d_rowptr[i] = excl;
            d_cursor[i] = excl;
            d_dinv[i]   = rsqrtf((float)(v + 1));  // deg includes self-loop, >= 1
        }
        __syncthreads();
        if (tid == 1023) s_carry = incl;
        __syncthreads();
    }
    if (threadIdx.x == 0) d_rowptr[NN] = s_carry;
}

// ---------------- wmma fp16 GEMM body: d_g = half(dinv[row] * (A @ W)) -------
// 256 threads = 8 warps, warp tile 16x64. A smem-staged (+8-half row pad);
// W smem-staged with +8-half row pad (conflict-free B LDSM). Sync-free mainloop.
template <int K, int N, int SRC>   // SRC 0: A = d_xh, 1: A = d_h16
__device__ __forceinline__ void gemm_wmma_body(int bid, const float* __restrict__ W,
                                               char* raw) {
    constexpr int N_WARPS = N / 64;          // 2 (N=128) or 1 (N=64)
    constexpr int M_WARPS = 8 / N_WARPS;     // 4 or 8
    constexpr int M_TILE  = M_WARPS * 16;    // 64 or 128
    constexpr int PK = K + 8;                // padded A row (halves)
    constexpr int PW = N + 8;                // padded W row (halves)
    constexpr int KSTEPS = K / 16;
    __half* Wsh = (__half*)raw;
    __half* As  = (__half*)(raw + K * PW * 2);
    const __half* __restrict__ A = (SRC == 0) ? d_xh : d_h16;

    int tid = threadIdx.x, warp = tid >> 5, lane = tid & 31;
    int warp_m = warp % M_WARPS;
    int warp_n = warp / M_WARPS;
    int m0 = bid * M_TILE;

    // stage W (fp32 -> fp16), padded row stride
    for (int i = tid; i < K * N / 2; i += 256) {
        int r = (i * 2) / N, c = (i * 2) % N;
        float2 w2 = *(const float2*)&W[r * N + c];
        *(__half2*)&Wsh[r * PW + c] = __floats2half2_rn(w2.x, w2.y);
    }
    // stage A tile coalesced (uint4 = 8 halves), padded row stride
    for (int idx = tid; idx < M_TILE * K / 8; idx += 256) {
        int r = idx / (K / 8);
        int c = (idx % (K / 8)) * 8;
        *(uint4*)&As[r * PK + c] = *(const uint4*)&A[(size_t)(m0 + r) * K + c];
    }
    __syncthreads();

    wmma::fragment<wmma::accumulator, 16, 16, 16, float> acc[4];
    #pragma unroll
    for (int nf = 0; nf < 4; nf++) wmma::fill_fragment(acc[nf], 0.0f);

    #pragma unroll
    for (int ks = 0; ks < KSTEPS; ks++) {
        wmma::fragment<wmma::matrix_a, 16, 16, 16, __half, wmma::row_major> a;
        wmma::load_matrix_sync(a, As + warp_m * 16 * PK + ks * 16, PK);
        #pragma unroll
        for (int nf = 0; nf < 4; nf++) {
            wmma::fragment<wmma::matrix_b, 16, 16, 16, __half, wmma::row_major> b;
            wmma::load_matrix_sync(b, Wsh + ks * 16 * PW + warp_n * 64 + nf * 16, PW);
            wmma::mma_sync(acc[nf], a, b, acc[nf]);
        }
    }

    // epilogue: bounce frags through smem (reuse), scale by dinv, fp16 store
    __syncthreads();
    float* Cs = (float*)raw + warp * (16 * 24);
    int r = lane >> 1;
    int c0 = (lane & 1) * 8;
    int row = m0 + warp_m * 16 + r;
    float s = (row < NN) ? d_dinv[row] : 0.0f;
    #pragma unroll
    for (int nf = 0; nf < 4; nf++) {
        wmma::store_matrix_sync(Cs, acc[nf], 24, wmma::mem_row_major);
        __syncwarp();
        if (row < NN) {
            float v[8];
            #pragma unroll
            for (int j = 0; j < 8; j++) v[j] = Cs[r * 24 + c0 + j] * s;
            __half2 h[4];
            #pragma unroll
            for (int j = 0; j < 4; j++)
                h[j] = __floats2half2_rn(v[2 * j], v[2 * j + 1]);
            *(uint4*)&d_g[(size_t)row * N + warp_n * 64 + nf * 16 + c0] = *(uint4*)h;
        }
        __syncwarp();
    }
}

template <int K, int N, int SRC>
__global__ void gemm_wmma_kernel(const float* __restrict__ W) {
    extern __shared__ __align__(16) char raw[];
    gemm_wmma_body<K, N, SRC>(blockIdx.x, W, raw);
}

// ---------------- fused: gemm1 (blocks 0..781) + CSR fill (rest) -------------
__global__ void gemm1_fill_kernel(const float* __restrict__ W1,
                                  const int* __restrict__ ei) {
    extern __shared__ __align__(16) char raw[];
    if (blockIdx.x < GEMM1_BLOCKS) {
        gemm_wmma_body<128, 128, 0>(blockIdx.x, W1, raw);
    } else {
        int e = (blockIdx.x - GEMM1_BLOCKS) * blockDim.x + threadIdx.x;
        if (e < NE) {
            int s = ei[e];
            int d = ei[NE + e];
            int p = atomicAdd(&d_cursor[d], 1);
            d_col[p] = s;
        }
    }
}

// ---------------- agg F=128: block per node, 64 threads, smem-staged cols ----
__global__ void agg128_kernel(const float* __restrict__ bias) {
    constexpr int T = 64;
    __shared__ int scol[T];
    int i = blockIdx.x;
    int f = threadIdx.x;       // owns features 2f, 2f+1
    const __half2* __restrict__ g2 = (const __half2*)d_g;

    __half2 h = g2[(size_t)i * T + f];          // self-loop term
    float2 acc;
    acc.x = __low2float(h);
    acc.y = __high2float(h);

    int s = d_rowptr[i], e = d_rowptr[i + 1];
    for (int base = s; base < e; base += T) {
        int n = min(T, e - base);
        __syncthreads();
        if (f < n) scol[f] = d_col[base + f];
        __syncthreads();
        int k = 0;
        for (; k + 8 <= n; k += 8) {
            #pragma unroll
            for (int j = 0; j < 8; j++) {
                int c = scol[k + j];
                __half2 v = g2[(size_t)c * T + f];
                acc.x += __low2float(v);
                acc.y += __high2float(v);
            }
        }
        for (; k < n; k++) {
            int c = scol[k];
            __half2 v = g2[(size_t)c * T + f];
            acc.x += __low2float(v);
            acc.y += __high2float(v);
        }
    }

    float di = d_dinv[i];
    float2 b2 = ((const float2*)bias)[f];
    ((__half2*)d_h16)[(size_t)i * T + f] =
        __floats2half2_rn(fmaxf(fmaf(di, acc.x, b2.x), 0.0f),
                          fmaxf(fmaf(di, acc.y, b2.y), 0.0f));
}

// ---------------- agg F=64: warp per node (8 nodes/256-thr block) ------------
// lane owns features 2l,2l+1 (half2); cols loaded coalesced once per 32 edges,
// broadcast via shfl — no smem, no block syncs; same accumulation order.
// MODE 0: relu -> d_h16 ;  MODE 2: no relu, fused pooling atomics
template <int MODE>
__global__ void agg64w_kernel(const float* __restrict__ bias,
                              const int* __restrict__ batch) {
    int warp = threadIdx.x >> 5, lane = threadIdx.x & 31;
    int i = blockIdx.x * 8 + warp;
    if (i >= NN) return;
    const __half2* __restrict__ g2 = (const __half2*)d_g;

    __half2 h = g2[(size_t)i * 32 + lane];      // self-loop term
    float2 acc;
    acc.x = __low2float(h);
    acc.y = __high2float(h);

    int s = d_rowptr[i], e = d_rowptr[i + 1];
    for (int base = s; base < e; base += 32) {
        int n = min(32, e - base);
        int idx = base + lane;
        int sc = d_col[(idx < e) ? idx : (e - 1)];   // coalesced, clamped
        int k = 0;
        for (; k + 8 <= n; k += 8) {
            #pragma unroll
            for (int j = 0; j < 8; j++) {
                int c = __shfl_sync(0xFFFFFFFFu, sc, k + j);
                __half2 v = g2[(size_t)c * 32 + lane];
                acc.x += __low2float(v);
                acc.y += __high2float(v);
            }
        }
        for (; k < n; k++) {
            int c = __shfl_sync(0xFFFFFFFFu, sc, k);
            __half2 v = g2[(size_t)c * 32 + lane];
            acc.x += __low2float(v);
            acc.y += __high2float(v);
        }
    }

    float di = d_dinv[i];
    float2 b2 = ((const float2*)bias)[lane];
    float rx = fmaf(di, acc.x, b2.x);
    float ry = fmaf(di, acc.y, b2.y);
    if (MODE == 0) {
        ((__half2*)d_h16)[(size_t)i * 32 + lane] =
            __floats2half2_rn(fmaxf(rx, 0.0f), fmaxf(ry, 0.0f));
    } else {
        int b = batch[i];
        atomicAdd(&d_pool[b * NH2 + 2 * lane + 0], rx);
        atomicAdd(&d_pool[b * NH2 + 2 * lane + 1], ry);
        if (lane == 0) atomicAdd(&d_gcnt[b], 1);
    }
}

// ---------------- final: sigmoid(mean) @ Wfc + bfc ---------------------------
__global__ void final_kernel(const float* __restrict__ Wfc,
                             const float* __restrict__ bfc,
                             float* __restrict__ out) {
    int gidx = blockIdx.x * (blockDim.x >> 5) + (threadIdx.x >> 5);
    int lane = threadIdx.x & 31;
    if (gidx >= NG) return;
    float cnt = fmaxf((float)d_gcnt[gidx], 1.0f);
    float s0 = d_pool[gidx * NH2 + lane];
    float s1 = d_pool[gidx * NH2 + 32 + lane];
    float z0 = 1.0f / (1.0f + expf(-s0 / cnt));
    float z1 = 1.0f / (1.0f + expf(-s1 / cnt));
    float p = z0 * Wfc[lane] + z1 * Wfc[lane + 32];
    #pragma unroll
    for (int o = 16; o > 0; o >>= 1) p += __shfl_down_sync(0xFFFFFFFFu, p, o);
    if (lane == 0) out[gidx] = p + bfc[0];
}

// ---------------- launch -----------------------------------------------------
extern "C" void kernel_launch(void* const* d_in, const int* in_sizes, int n_in,
                              void* d_out, int out_size) {
    const float* x     = (const float*)d_in[0];
    const int*   ei    = (const int*)d_in[1];
    const int*   batch = (const int*)d_in[2];
    const float* W1    = (const float*)d_in[3];
    const float* b1    = (const float*)d_in[4];
    const float* W2    = (const float*)d_in[5];
    const float* b2    = (const float*)d_in[6];
    const float* W3    = (const float*)d_in[7];
    const float* b3    = (const float*)d_in[8];
    const float* Wfc   = (const float*)d_in[9];
    const float* bfc   = (const float*)d_in[10];
    float* out = (float*)d_out;

    // raise dynamic-smem caps (host attribute set; idempotent, capture-safe)
    cudaFuncSetAttribute(gemm1_fill_kernel,
                         cudaFuncAttributeMaxDynamicSharedMemorySize,
                         GEMM_SMEM(128, 128));
    cudaFuncSetAttribute(gemm_wmma_kernel<128, 64, 1>,
                         cudaFuncAttributeMaxDynamicSharedMemorySize,
                         GEMM_SMEM(128, 64));
    cudaFuncSetAttribute(gemm_wmma_kernel<64, 64, 1>,
                         cudaFuncAttributeMaxDynamicSharedMemorySize,
                         GEMM_SMEM(64, 64));

    init_kernel<<<(NN + 255) / 256, 256>>>();
    count_convert_kernel<<<EDGE_BLOCKS + CONV_BLOCKS, 256>>>(ei, x);
    scan_kernel<<<1, 1024>>>();

    // layer 1 GEMM fused with CSR fill
    gemm1_fill_kernel
        <<<GEMM1_BLOCKS + EDGE_BLOCKS, 256, GEMM_SMEM(128, 128)>>>(W1, ei);
    agg128_kernel<<<NN, 64>>>(b1);

    // layer 2: 128 -> 64, relu
    gemm_wmma_kernel<128, 64, 1>
        <<<NROWS_PAD / 128, 256, GEMM_SMEM(128, 64)>>>(W2);
    agg64w_kernel<0><<<(NN + 7) / 8, 256>>>(b2, batch);

    // layer 3: 64 -> 64, no relu, fused pooling
    gemm_wmma_kernel<64, 64, 1>
        <<<NROWS_PAD / 128, 256, GEMM_SMEM(64, 64)>>>(W3);
    agg64w_kernel<2><<<(NN + 7) / 8, 256>>>(b3, batch);

    final_kernel<<<(NG + 7) / 8, 256>>>(Wfc, bfc, out);
}

// round 16
// speedup vs baseline: 1.3202x; 1.0116x over previous
#include <cuda_runtime.h>
#include <cuda_fp16.h>
#include <mma.h>
#include <math.h>
#include <stdint.h>

using namespace nvcuda;

// Problem constants
#define NN 50000
#define NE 800000
#define NF 128
#define NH 128
#define NH2 64
#define NG 512

#define NROWS_PAD 50048                       // 391 * 128 = 782 * 64, zero-padded
#define EDGE_BLOCKS ((NE + 255) / 256)        // 3125
#define CONV_BLOCKS ((NROWS_PAD * NF) / (256 * 8))  // 3128
#define GEMM1_BLOCKS (NROWS_PAD / 64)         // 782

// smem bytes: padded W tile + padded A tile (both conflict-free LDSM strides)
#define GEMM_SMEM(K, N) \
    ((K) * ((N) + 8) * 2 + (((N) == 128) ? 64 : 128) * ((K) + 8) * 2)

// ---------------- scratch (static device globals; no allocation) -------------
__device__ __half d_xh[(size_t)NROWS_PAD * NF];  // x in fp16 (padded rows = 0)
__device__ __half d_h16[(size_t)NROWS_PAD * NF]; // activations fp16
__device__ __half d_g[(size_t)NN * NF];          // dinv-scaled projected features
__device__ float  d_dinv[NN];
__device__ int    d_cnt[NN];
__device__ int    d_rowptr[NN + 1];
__device__ int    d_cursor[NN];
__device__ int    d_col[NE];
__device__ float  d_pool[NG * NH2];
__device__ int    d_gcnt[NG];

// ---------------- init ------------------------------------------------------
__global__ void init_kernel() {
    int i = blockIdx.x * blockDim.x + threadIdx.x;
    if (i < NN) d_cnt[i] = 0;
    if (i < NG * NH2) d_pool[i] = 0.0f;
    if (i < NG) d_gcnt[i] = 0;
}

// ---------------- fused: degree count + x -> fp16 convert --------------------
__global__ void count_convert_kernel(const int* __restrict__ ei,
                                     const float* __restrict__ x) {
    if (blockIdx.x < EDGE_BLOCKS) {
        int e = blockIdx.x * blockDim.x + threadIdx.x;
        if (e < NE) atomicAdd(&d_cnt[ei[NE + e]], 1);
    } else {
        int t = (blockIdx.x - EDGE_BLOCKS) * blockDim.x + threadIdx.x;
        size_t e0 = (size_t)t * 8;   // grid covers pad exactly
        if (e0 < (size_t)NN * NF) {
            float4 f0 = *(const float4*)&x[e0];
            float4 f1 = *(const float4*)&x[e0 + 4];
            __half2 h[4];
            h[0] = __floats2half2_rn(f0.x, f0.y);
            h[1] = __floats2half2_rn(f0.z, f0.w);
            h[2] = __floats2half2_rn(f1.x, f1.y);
            h[3] = __floats2half2_rn(f1.z, f1.w);
            *(uint4*)&d_xh[e0] = *(uint4*)h;
        } else {
            uint4 z = make_uint4(0, 0, 0, 0);
            *(uint4*)&d_xh[e0] = z;
        }
    }
}

// ---------------- single-block scan: rowptr/cursor/dinv ----------------------
__global__ void scan_kernel() {
    __shared__ int warp_sums[32];
    __shared__ int s_carry;
    int tid = threadIdx.x, lane = tid & 31, wid = tid >> 5;
    if (tid == 0) s_carry = 0;
    __syncthreads();
    for (int base = 0; base < NN; base += 1024) {
        int i = base + tid;
        int v = (i < NN) ? d_cnt[i] : 0;
        int x = v;
        #pragma unroll
        for (int o = 1; o < 32; o <<= 1) {
            int t = __shfl_up_sync(0xFFFFFFFFu, x, o);
            if (lane >= o) x += t;
        }
        if (lane == 31) warp_sums[wid] = x;
        __syncthreads();
        if (wid == 0) {
            int w = warp_sums[lane];
            #pragma unroll
            for (int o = 1; o < 32; o <<= 1) {
                int t = __shfl_up_sync(0xFFFFFFFFu, w, o);
                if (lane >= o) w += t;
            }
            warp_sums[lane] = w;
        }
        __syncthreads();
        int warp_prefix = (wid > 0) ? warp_sums[wid - 1] : 0;
        int incl = s_carry + warp_prefix + x;
        int excl = incl - v;
        if (i < NN) {
            d_rowptr[i] = excl;
            d_cursor[i] = excl;
            d_dinv[i]   = rsqrtf((float)(v + 1));  // deg includes self-loop, >= 1
        }
        __syncthreads();
        if (tid == 1023) s_carry = incl;
        __syncthreads();
    }
    if (threadIdx.x == 0) d_rowptr[NN] = s_carry;
}

// ---------------- wmma fp16 GEMM body: d_g = half(dinv[row] * (A @ W)) -------
// 256 threads = 8 warps, warp tile 16x64. A smem-staged (+8-half row pad);
// W smem-staged with +8-half row pad (conflict-free B LDSM). Sync-free mainloop.
template <int K, int N, int SRC>   // SRC 0: A = d_xh, 1: A = d_h16
__device__ __forceinline__ void gemm_wmma_body(int bid, const float* __restrict__ W,
                                               char* raw) {
    constexpr int N_WARPS = N / 64;          // 2 (N=128) or 1 (N=64)
    constexpr int M_WARPS = 8 / N_WARPS;     // 4 or 8
    constexpr int M_TILE  = M_WARPS * 16;    // 64 or 128
    constexpr int PK = K + 8;                // padded A row (halves)
    constexpr int PW = N + 8;                // padded W row (halves)
    constexpr int KSTEPS = K / 16;
    __half* Wsh = (__half*)raw;
    __half* As  = (__half*)(raw + K * PW * 2);
    const __half* __restrict__ A = (SRC == 0) ? d_xh : d_h16;

    int tid = threadIdx.x, warp = tid >> 5, lane = tid & 31;
    int warp_m = warp % M_WARPS;
    int warp_n = warp / M_WARPS;
    int m0 = bid * M_TILE;

    // stage W (fp32 -> fp16), padded row stride
    for (int i = tid; i < K * N / 2; i += 256) {
        int r = (i * 2) / N, c = (i * 2) % N;
        float2 w2 = *(const float2*)&W[r * N + c];
        *(__half2*)&Wsh[r * PW + c] = __floats2half2_rn(w2.x, w2.y);
    }
    // stage A tile coalesced (uint4 = 8 halves), padded row stride
    for (int idx = tid; idx < M_TILE * K / 8; idx += 256) {
        int r = idx / (K / 8);
        int c = (idx % (K / 8)) * 8;
        *(uint4*)&As[r * PK + c] = *(const uint4*)&A[(size_t)(m0 + r) * K + c];
    }
    __syncthreads();

    wmma::fragment<wmma::accumulator, 16, 16, 16, float> acc[4];
    #pragma unroll
    for (int nf = 0; nf < 4; nf++) wmma::fill_fragment(acc[nf], 0.0f);

    #pragma unroll
    for (int ks = 0; ks < KSTEPS; ks++) {
        wmma::fragment<wmma::matrix_a, 16, 16, 16, __half, wmma::row_major> a;
        wmma::load_matrix_sync(a, As + warp_m * 16 * PK + ks * 16, PK);
        #pragma unroll
        for (int nf = 0; nf < 4; nf++) {
            wmma::fragment<wmma::matrix_b, 16, 16, 16, __half, wmma::row_major> b;
            wmma::load_matrix_sync(b, Wsh + ks * 16 * PW + warp_n * 64 + nf * 16, PW);
            wmma::mma_sync(acc[nf], a, b, acc[nf]);
        }
    }

    // epilogue: bounce frags through smem (reuse), scale by dinv, fp16 store
    __syncthreads();
    float* Cs = (float*)raw + warp * (16 * 24);
    int r = lane >> 1;
    int c0 = (lane & 1) * 8;
    int row = m0 + warp_m * 16 + r;
    float s = (row < NN) ? d_dinv[row] : 0.0f;
    #pragma unroll
    for (int nf = 0; nf < 4; nf++) {
        wmma::store_matrix_sync(Cs, acc[nf], 24, wmma::mem_row_major);
        __syncwarp();
        if (row < NN) {
            float v[8];
            #pragma unroll
            for (int j = 0; j < 8; j++) v[j] = Cs[r * 24 + c0 + j] * s;
            __half2 h[4];
            #pragma unroll
            for (int j = 0; j < 4; j++)
                h[j] = __floats2half2_rn(v[2 * j], v[2 * j + 1]);
            *(uint4*)&d_g[(size_t)row * N + warp_n * 64 + nf * 16 + c0] = *(uint4*)h;
        }
        __syncwarp();
    }
}

template <int K, int N, int SRC>
__global__ void gemm_wmma_kernel(const float* __restrict__ W) {
    extern __shared__ __align__(16) char raw[];
    gemm_wmma_body<K, N, SRC>(blockIdx.x, W, raw);
}

// ---------------- fused: gemm1 (blocks 0..781) + CSR fill (rest) -------------
__global__ void gemm1_fill_kernel(const float* __restrict__ W1,
                                  const int* __restrict__ ei) {
    extern __shared__ __align__(16) char raw[];
    if (blockIdx.x < GEMM1_BLOCKS) {
        gemm_wmma_body<128, 128, 0>(blockIdx.x, W1, raw);
    } else {
        int e = (blockIdx.x - GEMM1_BLOCKS) * blockDim.x + threadIdx.x;
        if (e < NE) {
            int s = ei[e];
            int d = ei[NE + e];
            int p = atomicAdd(&d_cursor[d], 1);
            d_col[p] = s;
        }
    }
}

// ---------------- agg F=128: warp per node (8 nodes/256-thr block) -----------
// lane owns features 4l..4l+3 via uint2 (2 x half2); cols coalesced + shfl.
// out[i] = relu( dinv[i] * (g[i] + sum_c g[c]) + b ) -> d_h16
__global__ void agg128w_kernel(const float* __restrict__ bias) {
    int warp = threadIdx.x >> 5, lane = threadIdx.x & 31;
    int i = blockIdx.x * 8 + warp;
    if (i >= NN) return;
    const uint2* __restrict__ g4 = (const uint2*)d_g;   // row = 32 uint2

    uint2 hv = g4[(size_t)i * 32 + lane];               // self-loop term
    __half2 h0 = *(__half2*)&hv.x;
    __half2 h1 = *(__half2*)&hv.y;
    float4 acc;
    acc.x = __low2float(h0); acc.y = __high2float(h0);
    acc.z = __low2float(h1); acc.w = __high2float(h1);

    int s = d_rowptr[i], e = d_rowptr[i + 1];
    for (int base = s; base < e; base += 32) {
        int n = min(32, e - base);
        int idx = base + lane;
        int sc = d_col[(idx < e) ? idx : (e - 1)];      // coalesced, clamped
        int k = 0;
        for (; k + 8 <= n; k += 8) {
            #pragma unroll
            for (int j = 0; j < 8; j++) {
                int c = __shfl_sync(0xFFFFFFFFu, sc, k + j);
                uint2 v = g4[(size_t)c * 32 + lane];
                __half2 v0 = *(__half2*)&v.x;
                __half2 v1 = *(__half2*)&v.y;
                acc.x += __low2float(v0); acc.y += __high2float(v0);
                acc.z += __low2float(v1); acc.w += __high2float(v1);
            }
        }
        for (; k < n; k++) {
            int c = __shfl_sync(0xFFFFFFFFu, sc, k);
            uint2 v = g4[(size_t)c * 32 + lane];
            __half2 v0 = *(__half2*)&v.x;
            __half2 v1 = *(__half2*)&v.y;
            acc.x += __low2float(v0); acc.y += __high2float(v0);
            acc.z += __low2float(v1); acc.w += __high2float(v1);
        }
    }

    float di = d_dinv[i];
    float4 b4 = ((const float4*)bias)[lane];
    __half2 r0 = __floats2half2_rn(fmaxf(fmaf(di, acc.x, b4.x), 0.0f),
                                   fmaxf(fmaf(di, acc.y, b4.y), 0.0f));
    __half2 r1 = __floats2half2_rn(fmaxf(fmaf(di, acc.z, b4.z), 0.0f),
                                   fmaxf(fmaf(di, acc.w, b4.w), 0.0f));
    uint2 r;
    r.x = *(uint32_t*)&r0;
    r.y = *(uint32_t*)&r1;
    ((uint2*)d_h16)[(size_t)i * 32 + lane] = r;
}

// ---------------- agg F=64: warp per node (8 nodes/256-thr block) ------------
// lane owns features 2l,2l+1 (half2); cols coalesced + shfl broadcast.
// MODE 0: relu -> d_h16 ;  MODE 2: no relu, fused pooling atomics
template <int MODE>
__global__ void agg64w_kernel(const float* __restrict__ bias,
                              const int* __restrict__ batch) {
    int warp = threadIdx.x >> 5, lane = threadIdx.x & 31;
    int i = blockIdx.x * 8 + warp;
    if (i >= NN) return;
    const __half2* __restrict__ g2 = (const __half2*)d_g;

    __half2 h = g2[(size_t)i * 32 + lane];      // self-loop term
    float2 acc;
    acc.x = __low2float(h);
    acc.y = __high2float(h);

    int s = d_rowptr[i], e = d_rowptr[i + 1];
    for (int base = s; base < e; base += 32) {
        int n = min(32, e - base);
        int idx = base + lane;
        int sc = d_col[(idx < e) ? idx : (e - 1)];   // coalesced, clamped
        int k = 0;
        for (; k + 8 <= n; k += 8) {
            #pragma unroll
            for (int j = 0; j < 8; j++) {
                int c = __shfl_sync(0xFFFFFFFFu, sc, k + j);
                __half2 v = g2[(size_t)c * 32 + lane];
                acc.x += __low2float(v);
                acc.y += __high2float(v);
            }
        }
        for (; k < n; k++) {
            int c = __shfl_sync(0xFFFFFFFFu, sc, k);
            __half2 v = g2[(size_t)c * 32 + lane];
            acc.x += __low2float(v);
            acc.y += __high2float(v);
        }
    }

    float di = d_dinv[i];
    float2 b2 = ((const float2*)bias)[lane];
    float rx = fmaf(di, acc.x, b2.x);
    float ry = fmaf(di, acc.y, b2.y);
    if (MODE == 0) {
        ((__half2*)d_h16)[(size_t)i * 32 + lane] =
            __floats2half2_rn(fmaxf(rx, 0.0f), fmaxf(ry, 0.0f));
    } else {
        int b = batch[i];
        atomicAdd(&d_pool[b * NH2 + 2 * lane + 0], rx);
        atomicAdd(&d_pool[b * NH2 + 2 * lane + 1], ry);
        if (lane == 0) atomicAdd(&d_gcnt[b], 1);
    }
}

// ---------------- final: sigmoid(mean) @ Wfc + bfc ---------------------------
__global__ void final_kernel(const float* __restrict__ Wfc,
                             const float* __restrict__ bfc,
                             float* __restrict__ out) {
    int gidx = blockIdx.x * (blockDim.x >> 5) + (threadIdx.x >> 5);
    int lane = threadIdx.x & 31;
    if (gidx >= NG) return;
    float cnt = fmaxf((float)d_gcnt[gidx], 1.0f);
    float s0 = d_pool[gidx * NH2 + lane];
    float s1 = d_pool[gidx * NH2 + 32 + lane];
    float z0 = 1.0f / (1.0f + expf(-s0 / cnt));
    float z1 = 1.0f / (1.0f + expf(-s1 / cnt));
    float p = z0 * Wfc[lane] + z1 * Wfc[lane + 32];
    #pragma unroll
    for (int o = 16; o > 0; o >>= 1) p += __shfl_down_sync(0xFFFFFFFFu, p, o);
    if (lane == 0) out[gidx] = p + bfc[0];
}

// ---------------- launch -----------------------------------------------------
extern "C" void kernel_launch(void* const* d_in, const int* in_sizes, int n_in,
                              void* d_out, int out_size) {
    const float* x     = (const float*)d_in[0];
    const int*   ei    = (const int*)d_in[1];
    const int*   batch = (const int*)d_in[2];
    const float* W1    = (const float*)d_in[3];
    const float* b1    = (const float*)d_in[4];
    const float* W2    = (const float*)d_in[5];
    const float* b2    = (const float*)d_in[6];
    const float* W3    = (const float*)d_in[7];
    const float* b3    = (const float*)d_in[8];
    const float* Wfc   = (const float*)d_in[9];
    const float* bfc   = (const float*)d_in[10];
    float* out = (float*)d_out;

    // raise dynamic-smem caps (host attribute set; idempotent, capture-safe)
    cudaFuncSetAttribute(gemm1_fill_kernel,
                         cudaFuncAttributeMaxDynamicSharedMemorySize,
                         GEMM_SMEM(128, 128));
    cudaFuncSetAttribute(gemm_wmma_kernel<128, 64, 1>,
                         cudaFuncAttributeMaxDynamicSharedMemorySize,
                         GEMM_SMEM(128, 64));
    cudaFuncSetAttribute(gemm_wmma_kernel<64, 64, 1>,
                         cudaFuncAttributeMaxDynamicSharedMemorySize,
                         GEMM_SMEM(64, 64));

    init_kernel<<<(NN + 255) / 256, 256>>>();
    count_convert_kernel<<<EDGE_BLOCKS + CONV_BLOCKS, 256>>>(ei, x);
    scan_kernel<<<1, 1024>>>();

    // layer 1 GEMM fused with CSR fill
    gemm1_fill_kernel
        <<<GEMM1_BLOCKS + EDGE_BLOCKS, 256, GEMM_SMEM(128, 128)>>>(W1, ei);
    agg128w_kernel<<<(NN + 7) / 8, 256>>>(b1);

    // layer 2: 128 -> 64, relu
    gemm_wmma_kernel<128, 64, 1>
        <<<NROWS_PAD / 128, 256, GEMM_SMEM(128, 64)>>>(W2);
    agg64w_kernel<0><<<(NN + 7) / 8, 256>>>(b2, batch);

    // layer 3: 64 -> 64, no relu, fused pooling
    gemm_wmma_kernel<64, 64, 1>
        <<<NROWS_PAD / 128, 256, GEMM_SMEM(64, 64)>>>(W3);
    agg64w_kernel<2><<<(NN + 7) / 8, 256>>>(b3, batch);

    final_kernel<<<(NG + 7) / 8, 256>>>(Wfc, bfc, out);
}

// round 17
// speedup vs baseline: 1.6528x; 1.2520x over previous
#include <cuda_runtime.h>
#include <cuda_fp16.h>
#include <mma.h>
#include <math.h>
#include <stdint.h>

using namespace nvcuda;

// Problem constants
#define NN 50000
#define NE 800000
#define NF 128
#define NH 128
#define NH2 64
#define NG 512

#define NROWS_PAD 50048                       // 391 * 128 = 782 * 64, zero-padded
#define EDGE_BLOCKS ((NE + 255) / 256)        // 3125
#define CONV_BLOCKS ((NROWS_PAD * NF) / (256 * 8))  // 3128
#define GEMM1_BLOCKS (NROWS_PAD / 64)         // 782
#define SCAN_BLOCKS ((NN + 1023) / 1024)      // 49

// smem bytes: padded W tile + padded A tile (both conflict-free LDSM strides)
#define GEMM_SMEM(K, N) \
    ((K) * ((N) + 8) * 2 + (((N) == 128) ? 64 : 128) * ((K) + 8) * 2)

// ---------------- scratch (static device globals; no allocation) -------------
__device__ __half d_xh[(size_t)NROWS_PAD * NF];  // x in fp16 (padded rows = 0)
__device__ __half d_h16[(size_t)NROWS_PAD * NF]; // activations fp16
__device__ __half d_g[(size_t)NN * NF];          // dinv-scaled projected features
__device__ float  d_dinv[NN];
__device__ int    d_cnt[NN];
__device__ int    d_bsum[SCAN_BLOCKS];
__device__ int    d_rowptr[NN + 1];
__device__ int    d_cursor[NN];
__device__ int    d_col[NE];
__device__ float  d_pool[NG * NH2];
__device__ int    d_gcnt[NG];

// ---------------- init ------------------------------------------------------
__global__ void init_kernel() {
    int i = blockIdx.x * blockDim.x + threadIdx.x;
    if (i < NN) d_cnt[i] = 0;
    if (i < NG * NH2) d_pool[i] = 0.0f;
    if (i < NG) d_gcnt[i] = 0;
}

// ---------------- fused: degree count + x -> fp16 convert --------------------
__global__ void count_convert_kernel(const int* __restrict__ ei,
                                     const float* __restrict__ x) {
    if (blockIdx.x < EDGE_BLOCKS) {
        int e = blockIdx.x * blockDim.x + threadIdx.x;
        if (e < NE) atomicAdd(&d_cnt[ei[NE + e]], 1);
    } else {
        int t = (blockIdx.x - EDGE_BLOCKS) * blockDim.x + threadIdx.x;
        size_t e0 = (size_t)t * 8;   // grid covers pad exactly
        if (e0 < (size_t)NN * NF) {
            float4 f0 = *(const float4*)&x[e0];
            float4 f1 = *(const float4*)&x[e0 + 4];
            __half2 h[4];
            h[0] = __floats2half2_rn(f0.x, f0.y);
            h[1] = __floats2half2_rn(f0.z, f0.w);
            h[2] = __floats2half2_rn(f1.x, f1.y);
            h[3] = __floats2half2_rn(f1.z, f1.w);
            *(uint4*)&d_xh[e0] = *(uint4*)h;
        } else {
            uint4 z = make_uint4(0, 0, 0, 0);
            *(uint4*)&d_xh[e0] = z;
        }
    }
}

// ---------------- scan phase 1: per-block sums of d_cnt ----------------------
__global__ void scan1_kernel() {
    int tid = threadIdx.x, lane = tid & 31, wid = tid >> 5;
    int i = blockIdx.x * 1024 + tid;
    int v = (i < NN) ? d_cnt[i] : 0;
    #pragma unroll
    for (int o = 16; o > 0; o >>= 1) v += __shfl_down_sync(0xFFFFFFFFu, v, o);
    __shared__ int ws[32];
    if (lane == 0) ws[wid] = v;
    __syncthreads();
    if (wid == 0) {
        int w = ws[lane];
        #pragma unroll
        for (int o = 16; o > 0; o >>= 1) w += __shfl_down_sync(0xFFFFFFFFu, w, o);
        if (lane == 0) d_bsum[blockIdx.x] = w;
    }
}

// ---------------- scan phase 2: block-local scan + redundant offset ----------
__global__ void scan2_kernel() {
    int tid = threadIdx.x, lane = tid & 31, wid = tid >> 5;
    int b = blockIdx.x;
    __shared__ int s_off;
    __shared__ int ws[32];
    // offset = sum of bsum[0..b)  (warp 0, redundant per block — 49 values)
    if (wid == 0) {
        int v0 = (lane < b) ? d_bsum[lane] : 0;
        int v1 = (lane + 32 < b) ? d_bsum[lane + 32] : 0;
        int v = v0 + v1;
        #pragma unroll
        for (int o = 16; o > 0; o >>= 1) v += __shfl_down_sync(0xFFFFFFFFu, v, o);
        if (lane == 0) s_off = v;
    }
    __syncthreads();

    int i = b * 1024 + tid;
    int v = (i < NN) ? d_cnt[i] : 0;
    int x = v;
    #pragma unroll
    for (int o = 1; o < 32; o <<= 1) {
        int t = __shfl_up_sync(0xFFFFFFFFu, x, o);
        if (lane >= o) x += t;
    }
    if (lane == 31) ws[wid] = x;
    __syncthreads();
    if (wid == 0) {
        int w = ws[lane];
        #pragma unroll
        for (int o = 1; o < 32; o <<= 1) {
            int t = __shfl_up_sync(0xFFFFFFFFu, w, o);
            if (lane >= o) w += t;
        }
        ws[lane] = w;
    }
    __syncthreads();
    int warp_prefix = (wid > 0) ? ws[wid - 1] : 0;
    int excl = s_off + warp_prefix + x - v;
    if (i < NN) {
        d_rowptr[i] = excl;
        d_cursor[i] = excl;
        d_dinv[i]   = rsqrtf((float)(v + 1));  // deg includes self-loop, >= 1
    }
    if (b == 0 && tid == 0) d_rowptr[NN] = NE;  // total is a known constant
}

// ---------------- wmma fp16 GEMM body: d_g = half(dinv[row] * (A @ W)) -------
// 256 threads = 8 warps, warp tile 16x64. A smem-staged (+8-half row pad);
// W smem-staged with +8-half row pad (conflict-free B LDSM). Sync-free mainloop.
template <int K, int N, int SRC>   // SRC 0: A = d_xh, 1: A = d_h16
__device__ __forceinline__ void gemm_wmma_body(int bid, const float* __restrict__ W,
                                               char* raw) {
    constexpr int N_WARPS = N / 64;          // 2 (N=128) or 1 (N=64)
    constexpr int M_WARPS = 8 / N_WARPS;     // 4 or 8
    constexpr int M_TILE  = M_WARPS * 16;    // 64 or 128
    constexpr int PK = K + 8;                // padded A row (halves)
    constexpr int PW = N + 8;                // padded W row (halves)
    constexpr int KSTEPS = K / 16;
    __half* Wsh = (__half*)raw;
    __half* As  = (__half*)(raw + K * PW * 2);
    const __half* __restrict__ A = (SRC == 0) ? d_xh : d_h16;

    int tid = threadIdx.x, warp = tid >> 5, lane = tid & 31;
    int warp_m = warp % M_WARPS;
    int warp_n = warp / M_WARPS;
    int m0 = bid * M_TILE;

    // stage W (fp32 -> fp16), padded row stride
    for (int i = tid; i < K * N / 2; i += 256) {
        int r = (i * 2) / N, c = (i * 2) % N;
        float2 w2 = *(const float2*)&W[r * N + c];
        *(__half2*)&Wsh[r * PW + c] = __floats2half2_rn(w2.x, w2.y);
    }
    // stage A tile coalesced (uint4 = 8 halves), padded row stride
    for (int idx = tid; idx < M_TILE * K / 8; idx += 256) {
        int r = idx / (K / 8);
        int c = (idx % (K / 8)) * 8;
        *(uint4*)&As[r * PK + c] = *(const uint4*)&A[(size_t)(m0 + r) * K + c];
    }
    __syncthreads();

    wmma::fragment<wmma::accumulator, 16, 16, 16, float> acc[4];
    #pragma unroll
    for (int nf = 0; nf < 4; nf++) wmma::fill_fragment(acc[nf], 0.0f);

    #pragma unroll
    for (int ks = 0; ks < KSTEPS; ks++) {
        wmma::fragment<wmma::matrix_a, 16, 16, 16, __half, wmma::row_major> a;
        wmma::load_matrix_sync(a, As + warp_m * 16 * PK + ks * 16, PK);
        #pragma unroll
        for (int nf = 0; nf < 4; nf++) {
            wmma::fragment<wmma::matrix_b, 16, 16, 16, __half, wmma::row_major> b;
            wmma::load_matrix_sync(b, Wsh + ks * 16 * PW + warp_n * 64 + nf * 16, PW);
            wmma::mma_sync(acc[nf], a, b, acc[nf]);
        }
    }

    // epilogue: bounce frags through smem (reuse), scale by dinv, fp16 store
    __syncthreads();
    float* Cs = (float*)raw + warp * (16 * 24);
    int r = lane >> 1;
    int c0 = (lane & 1) * 8;
    int row = m0 + warp_m * 16 + r;
    float s = (row < NN) ? d_dinv[row] : 0.0f;
    #pragma unroll
    for (int nf = 0; nf < 4; nf++) {
        wmma::store_matrix_sync(Cs, acc[nf], 24, wmma::mem_row_major);
        __syncwarp();
        if (row < NN) {
            float v[8];
            #pragma unroll
            for (int j = 0; j < 8; j++) v[j] = Cs[r * 24 + c0 + j] * s;
            __half2 h[4];
            #pragma unroll
            for (int j = 0; j < 4; j++)
                h[j] = __floats2half2_rn(v[2 * j], v[2 * j + 1]);
            *(uint4*)&d_g[(size_t)row * N + warp_n * 64 + nf * 16 + c0] = *(uint4*)h;
        }
        __syncwarp();
    }
}

template <int K, int N, int SRC>
__global__ void gemm_wmma_kernel(const float* __restrict__ W) {
    extern __shared__ __align__(16) char raw[];
    gemm_wmma_body<K, N, SRC>(blockIdx.x, W, raw);
}

// ---------------- fused: gemm1 (blocks 0..781) + CSR fill (rest) -------------
__global__ void gemm1_fill_kernel(const float* __restrict__ W1,
                                  const int* __restrict__ ei) {
    extern __shared__ __align__(16) char raw[];
    if (blockIdx.x < GEMM1_BLOCKS) {
        gemm_wmma_body<128, 128, 0>(blockIdx.x, W1, raw);
    } else {
        int e = (blockIdx.x - GEMM1_BLOCKS) * blockDim.x + threadIdx.x;
        if (e < NE) {
            int s = ei[e];
            int d = ei[NE + e];
            int p = atomicAdd(&d_cursor[d], 1);
            d_col[p] = s;
        }
    }
}

// ---------------- agg F=128: warp per node (8 nodes/256-thr block) -----------
__global__ void agg128w_kernel(const float* __restrict__ bias) {
    int warp = threadIdx.x >> 5, lane = threadIdx.x & 31;
    int i = blockIdx.x * 8 + warp;
    if (i >= NN) return;
    const uint2* __restrict__ g4 = (const uint2*)d_g;   // row = 32 uint2

    uint2 hv = g4[(size_t)i * 32 + lane];               // self-loop term
    __half2 h0 = *(__half2*)&hv.x;
    __half2 h1 = *(__half2*)&hv.y;
    float4 acc;
    acc.x = __low2float(h0); acc.y = __high2float(h0);
    acc.z = __low2float(h1); acc.w = __high2float(h1);

    int s = d_rowptr[i], e = d_rowptr[i + 1];
    for (int base = s; base < e; base += 32) {
        int n = min(32, e - base);
        int idx = base + lane;
        int sc = d_col[(idx < e) ? idx : (e - 1)];      // coalesced, clamped
        int k = 0;
        for (; k + 8 <= n; k += 8) {
            #pragma unroll
            for (int j = 0; j < 8; j++) {
                int c = __shfl_sync(0xFFFFFFFFu, sc, k + j);
                uint2 v = g4[(size_t)c * 32 + lane];
                __half2 v0 = *(__half2*)&v.x;
                __half2 v1 = *(__half2*)&v.y;
                acc.x += __low2float(v0); acc.y += __high2float(v0);
                acc.z += __low2float(v1); acc.w += __high2float(v1);
            }
        }
        for (; k < n; k++) {
            int c = __shfl_sync(0xFFFFFFFFu, sc, k);
            uint2 v = g4[(size_t)c * 32 + lane];
            __half2 v0 = *(__half2*)&v.x;
            __half2 v1 = *(__half2*)&v.y;
            acc.x += __low2float(v0); acc.y += __high2float(v0);
            acc.z += __low2float(v1); acc.w += __high2float(v1);
        }
    }

    float di = d_dinv[i];
    float4 b4 = ((const float4*)bias)[lane];
    __half2 r0 = __floats2half2_rn(fmaxf(fmaf(di, acc.x, b4.x), 0.0f),
                                   fmaxf(fmaf(di, acc.y, b4.y), 0.0f));
    __half2 r1 = __floats2half2_rn(fmaxf(fmaf(di, acc.z, b4.z), 0.0f),
                                   fmaxf(fmaf(di, acc.w, b4.w), 0.0f));
    uint2 r;
    r.x = *(uint32_t*)&r0;
    r.y = *(uint32_t*)&r1;
    ((uint2*)d_h16)[(size_t)i * 32 + lane] = r;
}

// ---------------- agg F=64: warp per node (8 nodes/256-thr block) ------------
// MODE 0: relu -> d_h16 ;  MODE 2: no relu, fused pooling atomics
template <int MODE>
__global__ void agg64w_kernel(const float* __restrict__ bias,
                              const int* __restrict__ batch) {
    int warp = threadIdx.x >> 5, lane = threadIdx.x & 31;
    int i = blockIdx.x * 8 + warp;
    if (i >= NN) return;
    const __half2* __restrict__ g2 = (const __half2*)d_g;

    __half2 h = g2[(size_t)i * 32 + lane];      // self-loop term
    float2 acc;
    acc.x = __low2float(h);
    acc.y = __high2float(h);

    int s = d_rowptr[i], e = d_rowptr[i + 1];
    for (int base = s; base < e; base += 32) {
        int n = min(32, e - base);
        int idx = base + lane;
        int sc = d_col[(idx < e) ? idx : (e - 1)];   // coalesced, clamped
        int k = 0;
        for (; k + 8 <= n; k += 8) {
            #pragma unroll
            for (int j = 0; j < 8; j++) {
                int c = __shfl_sync(0xFFFFFFFFu, sc, k + j);
                __half2 v = g2[(size_t)c * 32 + lane];
                acc.x += __low2float(v);
                acc.y += __high2float(v);
            }
        }
        for (; k < n; k++) {
            int c = __shfl_sync(0xFFFFFFFFu, sc, k);
            __half2 v = g2[(size_t)c * 32 + lane];
            acc.x += __low2float(v);
            acc.y += __high2float(v);
        }
    }

    float di = d_dinv[i];
    float2 b2 = ((const float2*)bias)[lane];
    float rx = fmaf(di, acc.x, b2.x);
    float ry = fmaf(di, acc.y, b2.y);
    if (MODE == 0) {
        ((__half2*)d_h16)[(size_t)i * 32 + lane] =
            __floats2half2_rn(fmaxf(rx, 0.0f), fmaxf(ry, 0.0f));
    } else {
        int b = batch[i];
        atomicAdd(&d_pool[b * NH2 + 2 * lane + 0], rx);
        atomicAdd(&d_pool[b * NH2 + 2 * lane + 1], ry);
        if (lane == 0) atomicAdd(&d_gcnt[b], 1);
    }
}

// ---------------- final: sigmoid(mean) @ Wfc + bfc ---------------------------
__global__ void final_kernel(const float* __restrict__ Wfc,
                             const float* __restrict__ bfc,
                             float* __restrict__ out) {
    int gidx = blockIdx.x * (blockDim.x >> 5) + (threadIdx.x >> 5);
    int lane = threadIdx.x & 31;
    if (gidx >= NG) return;
    float cnt = fmaxf((float)d_gcnt[gidx], 1.0f);
    float s0 = d_pool[gidx * NH2 + lane];
    float s1 = d_pool[gidx * NH2 + 32 + lane];
    float z0 = 1.0f / (1.0f + expf(-s0 / cnt));
    float z1 = 1.0f / (1.0f + expf(-s1 / cnt));
    float p = z0 * Wfc[lane] + z1 * Wfc[lane + 32];
    #pragma unroll
    for (int o = 16; o > 0; o >>= 1) p += __shfl_down_sync(0xFFFFFFFFu, p, o);
    if (lane == 0) out[gidx] = p + bfc[0];
}

// ---------------- launch -----------------------------------------------------
extern "C" void kernel_launch(void* const* d_in, const int* in_sizes, int n_in,
                              void* d_out, int out_size) {
    const float* x     = (const float*)d_in[0];
    const int*   ei    = (const int*)d_in[1];
    const int*   batch = (const int*)d_in[2];
    const float* W1    = (const float*)d_in[3];
    const float* b1    = (const float*)d_in[4];
    const float* W2    = (const float*)d_in[5];
    const float* b2    = (const float*)d_in[6];
    const float* W3    = (const float*)d_in[7];
    const float* b3    = (const float*)d_in[8];
    const float* Wfc   = (const float*)d_in[9];
    const float* bfc   = (const float*)d_in[10];
    float* out = (float*)d_out;

    // raise dynamic-smem caps (host attribute set; idempotent, capture-safe)
    cudaFuncSetAttribute(gemm1_fill_kernel,
                         cudaFuncAttributeMaxDynamicSharedMemorySize,
                         GEMM_SMEM(128, 128));
    cudaFuncSetAttribute(gemm_wmma_kernel<128, 64, 1>,
                         cudaFuncAttributeMaxDynamicSharedMemorySize,
                         GEMM_SMEM(128, 64));
    cudaFuncSetAttribute(gemm_wmma_kernel<64, 64, 1>,
                         cudaFuncAttributeMaxDynamicSharedMemorySize,
                         GEMM_SMEM(64, 64));

    init_kernel<<<(NN + 255) / 256, 256>>>();
    count_convert_kernel<<<EDGE_BLOCKS + CONV_BLOCKS, 256>>>(ei, x);
    scan1_kernel<<<SCAN_BLOCKS, 1024>>>();
    scan2_kernel<<<SCAN_BLOCKS, 1024>>>();

    // layer 1 GEMM fused with CSR fill
    gemm1_fill_kernel
        <<<GEMM1_BLOCKS + EDGE_BLOCKS, 256, GEMM_SMEM(128, 128)>>>(W1, ei);
    agg128w_kernel<<<(NN + 7) / 8, 256>>>(b1);

    // layer 2: 128 -> 64, relu
    gemm_wmma_kernel<128, 64, 1>
        <<<NROWS_PAD / 128, 256, GEMM_SMEM(128, 64)>>>(W2);
    agg64w_kernel<0><<<(NN + 7) / 8, 256>>>(b2, batch);

    // layer 3: 64 -> 64, no relu, fused pooling
    gemm_wmma_kernel<64, 64, 1>
        <<<NROWS_PAD / 128, 256, GEMM_SMEM(64, 64)>>>(W3);
    agg64w_kernel<2><<<(NN + 7) / 8, 256>>>(b3, batch);

    final_kernel<<<(NG + 7) / 8, 256>>>(Wfc, bfc, out);
}